// round 10
// baseline (speedup 1.0000x reference)
#include <cuda_runtime.h>
#include <cuda_bf16.h>
#include <cuda_fp16.h>

// GCN: out = relu( D_in^{-1/2} * A * D_out^{-1/2} * (X W) + b )
// N=100000 nodes, E=1600000 edges, IN=64, HID=32.
// Inputs: features [N,64] f32, src [E] i32, dst [E] i32, W [64,32] f32, b [32] f32.
// Output: [N,32] f32.
//
// Graph (forked, 6 kernel nodes):
//   stream0: k_deg_in -> k_offsets(lookback scan) -> k_bucket ---\
//   stream2: k_deg_out -> k_gemm (h in fp16) ---------------------+-> k_aggregate
// Replay invariants (established by module-load zero-init, maintained by
// k_aggregate): g_deg_in = g_deg_out = 0, g_flag = 0.

#define N_NODES 100000
#define N_EDGES 1600000
#define IN_DIM  64
#define HID_DIM 32

#define SCAN_CHUNK 256
#define SCAN_NBLK  ((N_NODES + SCAN_CHUNK - 1) / SCAN_CHUNK)   // 391

#define GEMM_BLOCKS ((N_NODES + 63) / 64)                       // 1563

#define DEG_THREADS ((N_EDGES + 3) / 4)
#define DEG_BLOCKS  ((DEG_THREADS + 255) / 256)                 // 1563

#define BKT_EPT 2
#define BKT_THREADS ((N_EDGES + BKT_EPT - 1) / BKT_EPT)
#define BKT_BLOCKS  ((BKT_THREADS + 255) / 256)                 // 3125

// Scratch (no cudaMalloc allowed). Zero-initialized at module load.
__device__ int           g_deg_out[N_NODES];
__device__ int           g_deg_in[N_NODES];
__device__ __half        g_h16[N_NODES * HID_DIM];
__device__ int           g_off[N_NODES];
__device__ int           g_cursor[N_NODES];
__device__ int           g_srclist[N_EDGES];
__device__ volatile int  g_partv[SCAN_NBLK];
__device__ volatile int  g_flag[SCAN_NBLK];

// Host-side fork objects (host-only, created at load time)
namespace {
cudaStream_t g_s2 = nullptr;
cudaEvent_t  g_ev_fork = nullptr;
cudaEvent_t  g_ev_join = nullptr;
struct StreamInit {
    StreamInit() {
        cudaStreamCreateWithFlags(&g_s2, cudaStreamNonBlocking);
        cudaEventCreateWithFlags(&g_ev_fork, cudaEventDisableTiming);
        cudaEventCreateWithFlags(&g_ev_join, cudaEventDisableTiming);
    }
} g_stream_init;
}

__device__ __forceinline__ void fma4(float4& acc, float s, const float4& c) {
    acc.x += s * c.x;
    acc.y += s * c.y;
    acc.z += s * c.z;
    acc.w += s * c.w;
}

// ---------------------------------------------------------------------------
__global__ void k_deg_in(const int* __restrict__ dst) {
    int t = blockIdx.x * blockDim.x + threadIdx.x;
    int e = t * 4;
    if (e + 3 < N_EDGES) {
        int4 d4 = *(const int4*)&dst[e];
        atomicAdd(&g_deg_in[d4.x], 1);
        atomicAdd(&g_deg_in[d4.y], 1);
        atomicAdd(&g_deg_in[d4.z], 1);
        atomicAdd(&g_deg_in[d4.w], 1);
    } else {
        for (int j = e; j < N_EDGES; j++) atomicAdd(&g_deg_in[dst[j]], 1);
    }
}

__global__ void k_deg_out(const int* __restrict__ src) {
    int t = blockIdx.x * blockDim.x + threadIdx.x;
    int e = t * 4;
    if (e + 3 < N_EDGES) {
        int4 s4 = *(const int4*)&src[e];
        atomicAdd(&g_deg_out[s4.x], 1);
        atomicAdd(&g_deg_out[s4.y], 1);
        atomicAdd(&g_deg_out[s4.z], 1);
        atomicAdd(&g_deg_out[s4.w], 1);
    } else {
        for (int j = e; j < N_EDGES; j++) atomicAdd(&g_deg_out[src[j]], 1);
    }
}

// ---------------------------------------------------------------------------
// gemm: h16 = fp16( (X @ W) * norm_src ).  64 nodes per 256-thread block.
__global__ __launch_bounds__(256) void k_gemm(const float* __restrict__ X,
                                              const float* __restrict__ W) {
    __shared__ float sX[64 * IN_DIM];        // 16KB
    __shared__ float sW[IN_DIM * HID_DIM];   //  8KB

    int tid = threadIdx.x;
    int base = blockIdx.x * 64;

    const float4* W4 = (const float4*)W;
    float4* sW4 = (float4*)sW;
    #pragma unroll
    for (int i = tid; i < 512; i += 256) sW4[i] = W4[i];

    const float4* X4 = (const float4*)X;
    float4* sX4 = (float4*)sX;
    float4 z = make_float4(0.f, 0.f, 0.f, 0.f);
    #pragma unroll
    for (int i = tid; i < 1024; i += 256) {
        int node = base + (i >> 4);
        sX4[i] = (node < N_NODES) ? X4[node * 16 + (i & 15)] : z;
    }
    __syncthreads();

    int cg = tid & 7;            // col group: cols [cg*4, cg*4+4)
    int np = tid >> 3;           // node pair 0..31
    int n0 = np * 2, n1 = n0 + 1;

    float4 a0 = z, a1 = z;
    #pragma unroll
    for (int k = 0; k < IN_DIM; k += 4) {
        float4 x0 = *(const float4*)&sX[n0 * IN_DIM + k];
        float4 x1 = *(const float4*)&sX[n1 * IN_DIM + k];
        float4 c0 = *(const float4*)&sW[(k + 0) * HID_DIM + cg * 4];
        float4 c1 = *(const float4*)&sW[(k + 1) * HID_DIM + cg * 4];
        float4 c2 = *(const float4*)&sW[(k + 2) * HID_DIM + cg * 4];
        float4 c3 = *(const float4*)&sW[(k + 3) * HID_DIM + cg * 4];
        fma4(a0, x0.x, c0); fma4(a0, x0.y, c1);
        fma4(a0, x0.z, c2); fma4(a0, x0.w, c3);
        fma4(a1, x1.x, c0); fma4(a1, x1.y, c1);
        fma4(a1, x1.z, c2); fma4(a1, x1.w, c3);
    }

    int gn0 = base + n0;
    int gn1 = base + n1;
    if (gn0 < N_NODES) {
        float nrm = rsqrtf(fmaxf((float)g_deg_out[gn0], 1.0f));
        __half2* hrow = (__half2*)&g_h16[gn0 * HID_DIM];
        hrow[cg * 2 + 0] = __floats2half2_rn(a0.x * nrm, a0.y * nrm);
        hrow[cg * 2 + 1] = __floats2half2_rn(a0.z * nrm, a0.w * nrm);
    }
    if (gn1 < N_NODES) {
        float nrm = rsqrtf(fmaxf((float)g_deg_out[gn1], 1.0f));
        __half2* hrow = (__half2*)&g_h16[gn1 * HID_DIM];
        hrow[cg * 2 + 0] = __floats2half2_rn(a1.x * nrm, a1.y * nrm);
        hrow[cg * 2 + 1] = __floats2half2_rn(a1.z * nrm, a1.w * nrm);
    }
}

// ---------------------------------------------------------------------------
// Single-pass exclusive scan of deg_in with decoupled lookback.
// All 391 blocks are co-resident (256 thr, low regs) => spin-wait is safe.
__global__ __launch_bounds__(SCAN_CHUNK) void k_offsets() {
    __shared__ int s[SCAN_CHUNK];
    __shared__ int s_prefix;

    int t = threadIdx.x;
    int bid = blockIdx.x;
    int i = bid * SCAN_CHUNK + t;

    int v = (i < N_NODES) ? g_deg_in[i] : 0;
    s[t] = v;
    __syncthreads();
    #pragma unroll
    for (int o = 1; o < SCAN_CHUNK; o <<= 1) {
        int x = (t >= o) ? s[t - o] : 0;
        __syncthreads();
        s[t] += x;
        __syncthreads();
    }

    // publish this block's total
    if (t == SCAN_CHUNK - 1) {
        g_partv[bid] = s[t];
        __threadfence();
        g_flag[bid] = 1;
    }

    // lookback: warp 0 sums all predecessor partials
    if (t < 32) {
        int p = 0;
        for (int base2 = 0; base2 < bid; base2 += 32) {
            int j = base2 + t;
            int val = 0;
            if (j < bid) {
                while (g_flag[j] == 0) { }
                val = g_partv[j];
            }
            #pragma unroll
            for (int o = 16; o > 0; o >>= 1)
                val += __shfl_down_sync(0xFFFFFFFFu, val, o);
            if (t == 0) p += val;
        }
        if (t == 0) s_prefix = p;
    }
    __syncthreads();

    if (i < N_NODES) {
        int off = s[t] - v + s_prefix;
        g_off[i] = off;
        g_cursor[i] = off;
    }
}

// ---------------------------------------------------------------------------
// Counting-sort bucket fill: 2 edges per thread (latency-bound; max threads)
__global__ void k_bucket(const int* __restrict__ src,
                         const int* __restrict__ dst) {
    int t = blockIdx.x * blockDim.x + threadIdx.x;
    int e = t * 2;
    if (e + 1 < N_EDGES) {
        int2 s2 = *(const int2*)&src[e];
        int2 d2 = *(const int2*)&dst[e];
        int p0 = atomicAdd(&g_cursor[d2.x], 1);
        int p1 = atomicAdd(&g_cursor[d2.y], 1);
        g_srclist[p0] = s2.x;
        g_srclist[p1] = s2.y;
    } else if (e < N_EDGES) {
        g_srclist[atomicAdd(&g_cursor[dst[e]], 1)] = src[e];
    }
}

// ---------------------------------------------------------------------------
// Pull aggregation: one warp per node, lane = column. fp16 gather, fp32 acc.
// Fuses finalize + re-zeroes deg arrays and scan flags for next replay.
__global__ __launch_bounds__(256) void k_aggregate(float* __restrict__ out,
                                                   const float* __restrict__ b) {
    int gtid = blockIdx.x * blockDim.x + threadIdx.x;

    if (gtid < N_NODES) {
        g_deg_in[gtid] = 0;
        g_deg_out[gtid] = 0;
    }
    if (gtid < SCAN_NBLK) {
        g_flag[gtid] = 0;
    }

    int v = gtid >> 5;
    int lane = gtid & 31;
    if (v >= N_NODES) return;

    int off0 = g_off[v];
    int off1 = (v < N_NODES - 1) ? g_off[v + 1] : N_EDGES;

    const __half* h = (const __half*)g_h16;
    float acc = 0.0f;
    int i = off0;
    for (; i + 4 <= off1; i += 4) {
        int s0 = __ldg(&g_srclist[i + 0]);
        int s1 = __ldg(&g_srclist[i + 1]);
        int s2 = __ldg(&g_srclist[i + 2]);
        int s3 = __ldg(&g_srclist[i + 3]);
        float v0 = __half2float(__ldg(&h[s0 * HID_DIM + lane]));
        float v1 = __half2float(__ldg(&h[s1 * HID_DIM + lane]));
        float v2 = __half2float(__ldg(&h[s2 * HID_DIM + lane]));
        float v3 = __half2float(__ldg(&h[s3 * HID_DIM + lane]));
        acc += v0 + v1 + v2 + v3;
    }
    for (; i < off1; i++) {
        acc += __half2float(__ldg(&h[__ldg(&g_srclist[i]) * HID_DIM + lane]));
    }

    float deg = (float)(off1 - off0);
    float nrm = rsqrtf(fmaxf(deg, 1.0f));
    float r = acc * nrm + __ldg(&b[lane]);
    out[v * HID_DIM + lane] = fmaxf(r, 0.0f);
}

// ---------------------------------------------------------------------------
extern "C" void kernel_launch(void* const* d_in, const int* in_sizes, int n_in,
                              void* d_out, int out_size) {
    const float* features = (const float*)d_in[0];
    const int*   src      = (const int*)d_in[1];
    const int*   dst      = (const int*)d_in[2];
    const float* W        = (const float*)d_in[3];
    const float* b        = (const float*)d_in[4];
    float* out = (float*)d_out;

    // Fork at entry: branch B (deg_out -> gemm) independent of branch A.
    cudaEventRecord(g_ev_fork, 0);
    cudaStreamWaitEvent(g_s2, g_ev_fork, 0);

    // Branch B (side stream)
    k_deg_out<<<DEG_BLOCKS, 256, 0, g_s2>>>(src);
    k_gemm<<<GEMM_BLOCKS, 256, 0, g_s2>>>(features, W);
    cudaEventRecord(g_ev_join, g_s2);

    // Branch A (capture stream)
    k_deg_in<<<DEG_BLOCKS, 256>>>(dst);
    k_offsets<<<SCAN_NBLK, SCAN_CHUNK>>>();
    k_bucket<<<BKT_BLOCKS, 256>>>(src, dst);

    // Join
    cudaStreamWaitEvent(0, g_ev_join, 0);

    long long agg_threads = (long long)N_NODES * 32;
    k_aggregate<<<(int)((agg_threads + 255) / 256), 256>>>(out, b);
}

// round 11
// speedup vs baseline: 1.1387x; 1.1387x over previous
#include <cuda_runtime.h>
#include <cuda_bf16.h>
#include <cuda_fp16.h>

// GCN: out = relu( D_in^{-1/2} * A * D_out^{-1/2} * (X W) + b )
// N=100000 nodes, E=1600000 edges, IN=64, HID=32.
// Inputs: features [N,64] f32, src [E] i32, dst [E] i32, W [64,32] f32, b [32] f32.
// Output: [N,32] f32.
//
// Graph (forked, 7 kernel nodes):
//   stream0: k_deg_in -> k_scanA -> k_scanC -> k_bucket ----\
//   stream2: k_deg_out -> k_gemm (h in fp16) ----------------+-> k_aggregate
// Replay invariant (module-load zero-init, maintained by k_aggregate):
//   g_deg_in = g_deg_out = 0 at entry.
//
// k_aggregate: warp per node, split into two 16-lane halves; each half
// processes a different edge, each sublane loads a __half2 (2 cols). One
// warp LDG covers 2 edge-rows (128B) -> half the LSU slots of the fp32
// lane-per-col scheme.

#define N_NODES 100000
#define N_EDGES 1600000
#define IN_DIM  64
#define HID_DIM 32

#define SCAN_CHUNK 256
#define SCAN_NBLK  ((N_NODES + SCAN_CHUNK - 1) / SCAN_CHUNK)   // 391

#define GEMM_BLOCKS ((N_NODES + 63) / 64)                       // 1563

#define DEG_THREADS ((N_EDGES + 3) / 4)
#define DEG_BLOCKS  ((DEG_THREADS + 255) / 256)                 // 1563

#define BKT_EPT 2
#define BKT_THREADS ((N_EDGES + BKT_EPT - 1) / BKT_EPT)
#define BKT_BLOCKS  ((BKT_THREADS + 255) / 256)                 // 3125

// Scratch (no cudaMalloc allowed). Zero-initialized at module load.
__device__ int    g_deg_out[N_NODES];
__device__ int    g_deg_in[N_NODES];
__device__ __half g_h16[N_NODES * HID_DIM];
__device__ int    g_off[N_NODES];
__device__ int    g_cursor[N_NODES];
__device__ int    g_srclist[N_EDGES];
__device__ int    g_part[SCAN_NBLK];

// Host-side fork objects (host-only, created at load time)
namespace {
cudaStream_t g_s2 = nullptr;
cudaEvent_t  g_ev_fork = nullptr;
cudaEvent_t  g_ev_join = nullptr;
struct StreamInit {
    StreamInit() {
        cudaStreamCreateWithFlags(&g_s2, cudaStreamNonBlocking);
        cudaEventCreateWithFlags(&g_ev_fork, cudaEventDisableTiming);
        cudaEventCreateWithFlags(&g_ev_join, cudaEventDisableTiming);
    }
} g_stream_init;
}

__device__ __forceinline__ void fma4(float4& acc, float s, const float4& c) {
    acc.x += s * c.x;
    acc.y += s * c.y;
    acc.z += s * c.z;
    acc.w += s * c.w;
}

// ---------------------------------------------------------------------------
__global__ void k_deg_in(const int* __restrict__ dst) {
    int t = blockIdx.x * blockDim.x + threadIdx.x;
    int e = t * 4;
    if (e + 3 < N_EDGES) {
        int4 d4 = *(const int4*)&dst[e];
        atomicAdd(&g_deg_in[d4.x], 1);
        atomicAdd(&g_deg_in[d4.y], 1);
        atomicAdd(&g_deg_in[d4.z], 1);
        atomicAdd(&g_deg_in[d4.w], 1);
    } else {
        for (int j = e; j < N_EDGES; j++) atomicAdd(&g_deg_in[dst[j]], 1);
    }
}

__global__ void k_deg_out(const int* __restrict__ src) {
    int t = blockIdx.x * blockDim.x + threadIdx.x;
    int e = t * 4;
    if (e + 3 < N_EDGES) {
        int4 s4 = *(const int4*)&src[e];
        atomicAdd(&g_deg_out[s4.x], 1);
        atomicAdd(&g_deg_out[s4.y], 1);
        atomicAdd(&g_deg_out[s4.z], 1);
        atomicAdd(&g_deg_out[s4.w], 1);
    } else {
        for (int j = e; j < N_EDGES; j++) atomicAdd(&g_deg_out[src[j]], 1);
    }
}

// ---------------------------------------------------------------------------
// gemm: h16 = fp16( (X @ W) * norm_src ).  64 nodes per 256-thread block.
__global__ __launch_bounds__(256) void k_gemm(const float* __restrict__ X,
                                              const float* __restrict__ W) {
    __shared__ float sX[64 * IN_DIM];        // 16KB
    __shared__ float sW[IN_DIM * HID_DIM];   //  8KB

    int tid = threadIdx.x;
    int base = blockIdx.x * 64;

    const float4* W4 = (const float4*)W;
    float4* sW4 = (float4*)sW;
    #pragma unroll
    for (int i = tid; i < 512; i += 256) sW4[i] = W4[i];

    const float4* X4 = (const float4*)X;
    float4* sX4 = (float4*)sX;
    float4 z = make_float4(0.f, 0.f, 0.f, 0.f);
    #pragma unroll
    for (int i = tid; i < 1024; i += 256) {
        int node = base + (i >> 4);
        sX4[i] = (node < N_NODES) ? X4[node * 16 + (i & 15)] : z;
    }
    __syncthreads();

    int cg = tid & 7;            // col group: cols [cg*4, cg*4+4)
    int np = tid >> 3;           // node pair 0..31
    int n0 = np * 2, n1 = n0 + 1;

    float4 a0 = z, a1 = z;
    #pragma unroll
    for (int k = 0; k < IN_DIM; k += 4) {
        float4 x0 = *(const float4*)&sX[n0 * IN_DIM + k];
        float4 x1 = *(const float4*)&sX[n1 * IN_DIM + k];
        float4 c0 = *(const float4*)&sW[(k + 0) * HID_DIM + cg * 4];
        float4 c1 = *(const float4*)&sW[(k + 1) * HID_DIM + cg * 4];
        float4 c2 = *(const float4*)&sW[(k + 2) * HID_DIM + cg * 4];
        float4 c3 = *(const float4*)&sW[(k + 3) * HID_DIM + cg * 4];
        fma4(a0, x0.x, c0); fma4(a0, x0.y, c1);
        fma4(a0, x0.z, c2); fma4(a0, x0.w, c3);
        fma4(a1, x1.x, c0); fma4(a1, x1.y, c1);
        fma4(a1, x1.z, c2); fma4(a1, x1.w, c3);
    }

    int gn0 = base + n0;
    int gn1 = base + n1;
    if (gn0 < N_NODES) {
        float nrm = rsqrtf(fmaxf((float)g_deg_out[gn0], 1.0f));
        __half2* hrow = (__half2*)&g_h16[gn0 * HID_DIM];
        hrow[cg * 2 + 0] = __floats2half2_rn(a0.x * nrm, a0.y * nrm);
        hrow[cg * 2 + 1] = __floats2half2_rn(a0.z * nrm, a0.w * nrm);
    }
    if (gn1 < N_NODES) {
        float nrm = rsqrtf(fmaxf((float)g_deg_out[gn1], 1.0f));
        __half2* hrow = (__half2*)&g_h16[gn1 * HID_DIM];
        hrow[cg * 2 + 0] = __floats2half2_rn(a1.x * nrm, a1.y * nrm);
        hrow[cg * 2 + 1] = __floats2half2_rn(a1.z * nrm, a1.w * nrm);
    }
}

// ---------------------------------------------------------------------------
// Scan step A: per-block sums of deg_in (warp-shuffle reduce)
__global__ __launch_bounds__(SCAN_CHUNK) void k_scanA() {
    __shared__ int warp_sum[SCAN_CHUNK / 32];
    int t = threadIdx.x;
    int i = blockIdx.x * SCAN_CHUNK + t;
    int v = (i < N_NODES) ? g_deg_in[i] : 0;
    #pragma unroll
    for (int o = 16; o > 0; o >>= 1) v += __shfl_down_sync(0xFFFFFFFFu, v, o);
    if ((t & 31) == 0) warp_sum[t >> 5] = v;
    __syncthreads();
    if (t < 32) {
        int w = (t < SCAN_CHUNK / 32) ? warp_sum[t] : 0;
        #pragma unroll
        for (int o = 8; o > 0; o >>= 1) w += __shfl_down_sync(0xFFFFFFFFu, w, o);
        if (t == 0) g_part[blockIdx.x] = w;
    }
}

// ---------------------------------------------------------------------------
// Scan step C: block-local exclusive scan + local re-reduce of partials.
__global__ __launch_bounds__(SCAN_CHUNK) void k_scanC() {
    __shared__ int s[SCAN_CHUNK];
    __shared__ int s_red[SCAN_CHUNK / 32];
    __shared__ int s_prefix;

    int t = threadIdx.x;
    int bid = blockIdx.x;
    int i = bid * SCAN_CHUNK + t;

    {
        int p = 0;
        for (int j = t; j < SCAN_NBLK; j += SCAN_CHUNK) {
            if (j < bid) p += g_part[j];
        }
        #pragma unroll
        for (int o = 16; o > 0; o >>= 1) p += __shfl_down_sync(0xFFFFFFFFu, p, o);
        if ((t & 31) == 0) s_red[t >> 5] = p;
        __syncthreads();
        if (t < 32) {
            int w = (t < SCAN_CHUNK / 32) ? s_red[t] : 0;
            #pragma unroll
            for (int o = 8; o > 0; o >>= 1) w += __shfl_down_sync(0xFFFFFFFFu, w, o);
            if (t == 0) s_prefix = w;
        }
    }

    int v = (i < N_NODES) ? g_deg_in[i] : 0;
    s[t] = v;
    __syncthreads();
    #pragma unroll
    for (int o = 1; o < SCAN_CHUNK; o <<= 1) {
        int x = (t >= o) ? s[t - o] : 0;
        __syncthreads();
        s[t] += x;
        __syncthreads();
    }
    if (i < N_NODES) {
        int off = s[t] - v + s_prefix;
        g_off[i] = off;
        g_cursor[i] = off;
    }
}

// ---------------------------------------------------------------------------
// Counting-sort bucket fill: 2 edges per thread
__global__ void k_bucket(const int* __restrict__ src,
                         const int* __restrict__ dst) {
    int t = blockIdx.x * blockDim.x + threadIdx.x;
    int e = t * 2;
    if (e + 1 < N_EDGES) {
        int2 s2 = *(const int2*)&src[e];
        int2 d2 = *(const int2*)&dst[e];
        int p0 = atomicAdd(&g_cursor[d2.x], 1);
        int p1 = atomicAdd(&g_cursor[d2.y], 1);
        g_srclist[p0] = s2.x;
        g_srclist[p1] = s2.y;
    } else if (e < N_EDGES) {
        g_srclist[atomicAdd(&g_cursor[dst[e]], 1)] = src[e];
    }
}

// ---------------------------------------------------------------------------
// Pull aggregation: warp per node; two 16-lane halves process different
// edges; sublane s owns column pair (2s, 2s+1) via __half2 loads.
// Fuses finalize + re-zeroes deg arrays for next replay.
__global__ __launch_bounds__(256) void k_aggregate(float* __restrict__ out,
                                                   const float* __restrict__ b) {
    int gtid = blockIdx.x * blockDim.x + threadIdx.x;

    if (gtid < N_NODES) {
        g_deg_in[gtid] = 0;
        g_deg_out[gtid] = 0;
    }

    int v = gtid >> 5;
    int lane = gtid & 31;
    if (v >= N_NODES) return;

    int half = lane >> 4;        // 0 or 1: which edge of the pair
    int sub  = lane & 15;        // column pair index

    int off0 = g_off[v];
    int off1 = (v < N_NODES - 1) ? g_off[v + 1] : N_EDGES;

    const __half2* h2 = (const __half2*)g_h16;   // 16 half2 per node row

    float accx = 0.0f, accy = 0.0f;
    int i = off0 + half;
    // 4 edges per warp-iteration (2 per half), unrolled for MLP
    for (; i + 2 < off1; i += 4) {
        int sA = __ldg(&g_srclist[i]);
        int sB = __ldg(&g_srclist[i + 2]);
        __half2 hA = __ldg(&h2[sA * 16 + sub]);
        __half2 hB = __ldg(&h2[sB * 16 + sub]);
        float2 fA = __half22float2(hA);
        float2 fB = __half22float2(hB);
        accx += fA.x + fB.x;
        accy += fA.y + fB.y;
    }
    for (; i < off1; i += 2) {
        int sA = __ldg(&g_srclist[i]);
        __half2 hA = __ldg(&h2[sA * 16 + sub]);
        float2 fA = __half22float2(hA);
        accx += fA.x;
        accy += fA.y;
    }

    // merge the two half-warps (lane L += lane L+16)
    accx += __shfl_down_sync(0xFFFFFFFFu, accx, 16);
    accy += __shfl_down_sync(0xFFFFFFFFu, accy, 16);

    if (half == 0) {
        float deg = (float)(off1 - off0);
        float nrm = rsqrtf(fmaxf(deg, 1.0f));
        float2 bb = __ldg(&((const float2*)b)[sub]);
        float rx = accx * nrm + bb.x;
        float ry = accy * nrm + bb.y;
        float2 r = make_float2(fmaxf(rx, 0.0f), fmaxf(ry, 0.0f));
        ((float2*)&out[v * HID_DIM])[sub] = r;
    }
}

// ---------------------------------------------------------------------------
extern "C" void kernel_launch(void* const* d_in, const int* in_sizes, int n_in,
                              void* d_out, int out_size) {
    const float* features = (const float*)d_in[0];
    const int*   src      = (const int*)d_in[1];
    const int*   dst      = (const int*)d_in[2];
    const float* W        = (const float*)d_in[3];
    const float* b        = (const float*)d_in[4];
    float* out = (float*)d_out;

    // Fork at entry: branch B (deg_out -> gemm) independent of branch A.
    cudaEventRecord(g_ev_fork, 0);
    cudaStreamWaitEvent(g_s2, g_ev_fork, 0);

    // Branch B (side stream)
    k_deg_out<<<DEG_BLOCKS, 256, 0, g_s2>>>(src);
    k_gemm<<<GEMM_BLOCKS, 256, 0, g_s2>>>(features, W);
    cudaEventRecord(g_ev_join, g_s2);

    // Branch A (capture stream)
    k_deg_in<<<DEG_BLOCKS, 256>>>(dst);
    k_scanA<<<SCAN_NBLK, SCAN_CHUNK>>>();
    k_scanC<<<SCAN_NBLK, SCAN_CHUNK>>>();
    k_bucket<<<BKT_BLOCKS, 256>>>(src, dst);

    // Join
    cudaStreamWaitEvent(0, g_ev_join, 0);

    long long agg_threads = (long long)N_NODES * 32;
    k_aggregate<<<(int)((agg_threads + 255) / 256), 256>>>(out, b);
}